// round 11
// baseline (speedup 1.0000x reference)
#include <cuda_runtime.h>
#include <cuda_bf16.h>
#include <cstdint>
#include <math.h>

#define HW    16384
#define WIMG  128
#define HIMG  128
#define DIM   384
#define BATCH 4

/* ---------------- scratch ---------------- */
__device__ __align__(16) __nv_bfloat16 g_xbf [BATCH * DIM * HW];
__device__ __align__(16) __nv_bfloat16 g_qkv [BATCH * 3 * DIM * HW];
__device__ __align__(16) __nv_bfloat16 g_mix [BATCH * DIM * HW];
__device__ __align__(16) __nv_bfloat16 g_wqkv[3 * DIM * DIM];
__device__ __align__(16) __nv_bfloat16 g_wpro[DIM * DIM];
__device__ float g_sumsq[64];
__device__ float g_dots[256];
__device__ float g_attn[256];

/* ---------------- PTX macros ---------------- */
#define CP_ASYNC16(saddr, gaddr) \
    asm volatile("cp.async.cg.shared.global [%0], [%1], 16;\n" :: "r"(saddr), "l"(gaddr))
#define CP_COMMIT() asm volatile("cp.async.commit_group;\n" ::: "memory")
#define CP_WAIT1()  asm volatile("cp.async.wait_group 1;\n" ::: "memory")
#define CP_WAIT2()  asm volatile("cp.async.wait_group 2;\n" ::: "memory")
#define LDSM_X4(r0, r1, r2, r3, addr) \
    asm volatile("ldmatrix.sync.aligned.m8n8.x4.shared.b16 {%0,%1,%2,%3}, [%4];\n" \
                 : "=r"(r0), "=r"(r1), "=r"(r2), "=r"(r3) : "r"(addr))
#define LDSM_X2T(r0, r1, addr) \
    asm volatile("ldmatrix.sync.aligned.m8n8.x2.trans.shared.b16 {%0,%1}, [%2];\n" \
                 : "=r"(r0), "=r"(r1) : "r"(addr))
#define MMA16816(c0, c1, c2, c3, a0, a1, a2, a3, b0, b1) \
    asm volatile("mma.sync.aligned.m16n8k16.row.col.f32.bf16.bf16.f32 " \
                 "{%0,%1,%2,%3}, {%4,%5,%6,%7}, {%8,%9}, {%0,%1,%2,%3};\n" \
                 : "+f"(c0), "+f"(c1), "+f"(c2), "+f"(c3) \
                 : "r"(a0), "r"(a1), "r"(a2), "r"(a3), "r"(b0), "r"(b1))

#define AS_SLOT (128 * 40)
#define BS_SLOT (32 * 136)
#define SMEM_GEMM ((4 * AS_SLOT + 4 * BS_SLOT) * 2)

/* ---------------- tiny init ---------------- */
__global__ void zero_kernel() {
    int t = threadIdx.x;
    if (t < 64)  g_sumsq[t] = 0.f;
    if (t < 256) g_dots[t]  = 0.f;
}

/* ---------------- conversions fp32 -> bf16 ---------------- */
__global__ __launch_bounds__(256) void convert_x(const float* __restrict__ x) {
    int i = blockIdx.x * 256 + threadIdx.x;
    float4 v = ((const float4*)x)[i];
    __nv_bfloat162* o = (__nv_bfloat162*)g_xbf;
    o[2 * i]     = __floats2bfloat162_rn(v.x, v.y);
    o[2 * i + 1] = __floats2bfloat162_rn(v.z, v.w);
}

__global__ __launch_bounds__(256) void convert_w(const float* __restrict__ wq,
                                                 const float* __restrict__ wp) {
    int i = blockIdx.x * 256 + threadIdx.x;
    if (i < 3 * DIM * DIM) {
        g_wqkv[i] = __float2bfloat16(wq[i]);
    } else {
        g_wpro[i - 3 * DIM * DIM] = __float2bfloat16(wp[i - 3 * DIM * DIM]);
    }
}

/* ================= GEMM load macro (shared by both gemms) ================= */
#define GEMM_LOAD(slot, k0) do { \
    const __nv_bfloat16* ap_ = Ap + (size_t)arow * DIM + (k0) + acol; \
    unsigned int sa_ = asBase + (unsigned int)((((slot) * AS_SLOT) + arow * 40 + acol) * 2); \
    CP_ASYNC16(sa_, ap_); \
    CP_ASYNC16(sa_ + (unsigned int)(64 * 40 * 2), ap_ + 64 * DIM); \
    const __nv_bfloat16* bp_ = Bp + (size_t)((k0) + brow) * HW + bcol; \
    unsigned int sb_ = bsBase + (unsigned int)((((slot) * BS_SLOT) + brow * 136 + bcol) * 2); \
    CP_ASYNC16(sb_, bp_); \
    CP_ASYNC16(sb_ + (unsigned int)(16 * 136 * 2), bp_ + 16 * HW); \
} while (0)

#define GEMM_COMPUTE(slot) do { \
    for (int ks = 0; ks < 2; ks++) { \
        unsigned int af[4][4]; \
        unsigned int bfr[4][2]; \
        for (int mi = 0; mi < 4; mi++) { \
            unsigned int aaddr = asBase + (unsigned int)( \
                (((slot) * AS_SLOT) + (wm * 64 + mi * 16 + (ln & 15)) * 40 + \
                 ks * 16 + ((ln >> 4) << 3)) * 2); \
            LDSM_X4(af[mi][0], af[mi][1], af[mi][2], af[mi][3], aaddr); \
        } \
        for (int ni = 0; ni < 4; ni++) { \
            unsigned int baddr = bsBase + (unsigned int)( \
                (((slot) * BS_SLOT) + (ks * 16 + (ln & 15)) * 136 + wn * 32 + ni * 8) * 2); \
            LDSM_X2T(bfr[ni][0], bfr[ni][1], baddr); \
        } \
        for (int mi = 0; mi < 4; mi++) { \
            for (int ni = 0; ni < 4; ni++) { \
                MMA16816(acc[mi][ni][0], acc[mi][ni][1], acc[mi][ni][2], acc[mi][ni][3], \
                         af[mi][0], af[mi][1], af[mi][2], af[mi][3], \
                         bfr[ni][0], bfr[ni][1]); \
            } \
        } \
    } \
} while (0)

/* ---------------- GEMM 1: qkv = Wqkv(1152x384) @ Xb, 4-stage ---------------- */
__global__ __launch_bounds__(256) void gemm_qkv_tc(const float* __restrict__ bias) {
    extern __shared__ __nv_bfloat16 dsm[];

    int tid = threadIdx.x;
    int bb  = blockIdx.x >> 7;
    int n0  = (blockIdx.x & 127) << 7;
    int m0  = blockIdx.y << 7;
    const __nv_bfloat16* Ap = g_wqkv + (size_t)m0 * DIM;
    const __nv_bfloat16* Bp = g_xbf + (size_t)bb * DIM * HW + n0;

    unsigned int asBase = (unsigned int)__cvta_generic_to_shared(dsm);
    unsigned int bsBase = asBase + (unsigned int)(4 * AS_SLOT * 2);

    int arow = tid >> 2, acol = (tid & 3) * 8;
    int brow = tid >> 4, bcol = (tid & 15) * 8;
    int wrp = tid >> 5, ln = tid & 31;
    int wm = wrp >> 2, wn = wrp & 3;

    float acc[4][4][4];
#pragma unroll
    for (int i = 0; i < 4; i++)
#pragma unroll
        for (int j = 0; j < 4; j++)
#pragma unroll
            for (int r = 0; r < 4; r++) { acc[i][j][r] = 0.f; }

    GEMM_LOAD(0, 0);  CP_COMMIT();
    GEMM_LOAD(1, 32); CP_COMMIT();
    GEMM_LOAD(2, 64); CP_COMMIT();

    for (int kt = 0; kt < 12; kt++) {
        CP_WAIT2();
        __syncthreads();
        if (kt + 3 < 12) { GEMM_LOAD((kt + 3) & 3, (kt + 3) * 32); }
        CP_COMMIT();
        int slot = kt & 3;
        GEMM_COMPUTE(slot);
    }

    int rbase = m0 + wm * 64;
    int cbase = n0 + wn * 32 + (ln & 3) * 2;
#pragma unroll
    for (int mi = 0; mi < 4; mi++) {
        int r0 = rbase + mi * 16 + (ln >> 2);
        float bv0 = bias[r0];
        float bv1 = bias[r0 + 8];
#pragma unroll
        for (int ni = 0; ni < 4; ni++) {
            int c = cbase + ni * 8;
            __nv_bfloat162* d0 = (__nv_bfloat162*)&g_qkv[((size_t)bb * 1152 + r0) * HW + c];
            __nv_bfloat162* d1 = (__nv_bfloat162*)&g_qkv[((size_t)bb * 1152 + r0 + 8) * HW + c];
            *d0 = __floats2bfloat162_rn(acc[mi][ni][0] + bv0, acc[mi][ni][1] + bv0);
            *d1 = __floats2bfloat162_rn(acc[mi][ni][2] + bv1, acc[mi][ni][3] + bv1);
        }
    }
}

/* ---------------- GEMM 2: out = Wproj @ mix + bias + residual, 4-stage ------- */
__global__ __launch_bounds__(256) void gemm_proj_tc(const float* __restrict__ bias,
                                                    const float* __restrict__ resid,
                                                    float* __restrict__ outf) {
    extern __shared__ __nv_bfloat16 dsm[];

    int tid = threadIdx.x;
    int bb  = blockIdx.x >> 7;
    int n0  = (blockIdx.x & 127) << 7;
    int m0  = blockIdx.y << 7;
    const __nv_bfloat16* Ap = g_wpro + (size_t)m0 * DIM;
    const __nv_bfloat16* Bp = g_mix + (size_t)bb * DIM * HW + n0;

    unsigned int asBase = (unsigned int)__cvta_generic_to_shared(dsm);
    unsigned int bsBase = asBase + (unsigned int)(4 * AS_SLOT * 2);

    int arow = tid >> 2, acol = (tid & 3) * 8;
    int brow = tid >> 4, bcol = (tid & 15) * 8;
    int wrp = tid >> 5, ln = tid & 31;
    int wm = wrp >> 2, wn = wrp & 3;

    float acc[4][4][4];
#pragma unroll
    for (int i = 0; i < 4; i++)
#pragma unroll
        for (int j = 0; j < 4; j++)
#pragma unroll
            for (int r = 0; r < 4; r++) { acc[i][j][r] = 0.f; }

    GEMM_LOAD(0, 0);  CP_COMMIT();
    GEMM_LOAD(1, 32); CP_COMMIT();
    GEMM_LOAD(2, 64); CP_COMMIT();

    for (int kt = 0; kt < 12; kt++) {
        CP_WAIT2();
        __syncthreads();
        if (kt + 3 < 12) { GEMM_LOAD((kt + 3) & 3, (kt + 3) * 32); }
        CP_COMMIT();
        int slot = kt & 3;
        GEMM_COMPUTE(slot);
    }

    int rbase = m0 + wm * 64;
    int cbase = n0 + wn * 32 + (ln & 3) * 2;
#pragma unroll
    for (int mi = 0; mi < 4; mi++) {
        int r0 = rbase + mi * 16 + (ln >> 2);
        float bv0 = bias[r0];
        float bv1 = bias[r0 + 8];
#pragma unroll
        for (int ni = 0; ni < 4; ni++) {
            int c = cbase + ni * 8;
            size_t o0 = ((size_t)bb * DIM + r0) * HW + c;
            size_t o1 = ((size_t)bb * DIM + r0 + 8) * HW + c;
            float2 x0 = *(const float2*)(resid + o0);
            float2 x1 = *(const float2*)(resid + o1);
            float2 v0, v1;
            v0.x = acc[mi][ni][0] + bv0 + x0.x;
            v0.y = acc[mi][ni][1] + bv0 + x0.y;
            v1.x = acc[mi][ni][2] + bv1 + x1.x;
            v1.y = acc[mi][ni][3] + bv1 + x1.y;
            *(float2*)(outf + o0) = v0;
            *(float2*)(outf + o1) = v1;
        }
    }
}

/* ======== fused dwconv(q,k) + Gram dots + sumsq ========
   Block: (strip of 8 rows) x (one c in 0..47) x batch. 256 threads.
   Phase 1: for 16 channels (8 q-heads + 8 k-heads at this c), cp.async-staged
   3x3 dwconv -> smem qd/kd (bf16). Phase 2: per-pixel 8x8 outer product. */
#define ISSUE_CH(cc, s) do { \
    int ch_ = ((cc) < 8) ? ((cc) * 48 + c) : (384 + ((cc) - 8) * 48 + c); \
    const __nv_bfloat16* src_ = g_qkv + ((size_t)bi * 1152 + ch_) * HW; \
    if (tid < 160) { \
        int row_ = tid >> 4; \
        int col_ = (tid & 15) * 8; \
        int gy_ = y0 + row_ - 1; \
        int off_ = ((s) * 1280) + row_ * 128 + col_; \
        if (gy_ >= 0 && gy_ < HIMG) { \
            unsigned int dst_ = ibBase + (unsigned int)(off_ * 2); \
            CP_ASYNC16(dst_, src_ + gy_ * WIMG + col_); \
        } else { \
            *(float4*)((char*)inbuf + off_ * 2) = make_float4(0.f, 0.f, 0.f, 0.f); \
        } \
    } \
} while (0)

__global__ __launch_bounds__(256) void dwqk_dots_kernel(const float* __restrict__ wdw,
                                                        const float* __restrict__ bdw) {
    __shared__ __align__(16) __nv_bfloat16 inbuf[2][1280];
    __shared__ __align__(16) __nv_bfloat16 qd_s[8][1024];
    __shared__ __align__(16) __nv_bfloat16 kd_s[8][1024];
    __shared__ float red[80];

    int tid = threadIdx.x;
    int strip = blockIdx.x;     /* 0..15 */
    int c  = blockIdx.y;        /* 0..47 */
    int bi = blockIdx.z;        /* 0..3  */
    int y0 = strip * 8;

    unsigned int ibBase = (unsigned int)__cvta_generic_to_shared(&inbuf[0][0]);

    float ssq[16];
#pragma unroll
    for (int i = 0; i < 16; i++) { ssq[i] = 0.f; }

    int r  = tid >> 5;          /* 0..7 local out row  */
    int c0 = (tid & 31) * 4;    /* 0..124 out col base */
    int px0 = tid * 4;

    ISSUE_CH(0, 0);
    CP_COMMIT();

    for (int cc = 0; cc < 16; cc++) {
        if (cc < 15) { ISSUE_CH(cc + 1, (cc + 1) & 1); }
        CP_COMMIT();
        CP_WAIT1();
        __syncthreads();

        int ch = (cc < 8) ? (cc * 48 + c) : (384 + (cc - 8) * 48 + c);
        float w[9];
#pragma unroll
        for (int i = 0; i < 9; i++) { w[i] = wdw[ch * 9 + i]; }
        float bv = bdw[ch];

        const __nv_bfloat16* ib = &inbuf[cc & 1][0];
        float vals[3][6];
#pragma unroll
        for (int dy = 0; dy < 3; dy++) {
#pragma unroll
            for (int dx = 0; dx < 6; dx++) {
                int cin = c0 - 1 + dx;
                vals[dy][dx] = (cin >= 0 && cin < 128)
                               ? __bfloat162float(ib[(r + dy) * 128 + cin]) : 0.f;
            }
        }
        float o[4];
#pragma unroll
        for (int j = 0; j < 4; j++) {
            float s = bv;
#pragma unroll
            for (int dy = 0; dy < 3; dy++) {
#pragma unroll
                for (int dx = 0; dx < 3; dx++) {
                    s = fmaf(w[dy * 3 + dx], vals[dy][j + dx], s);
                }
            }
            o[j] = s;
            ssq[cc] = fmaf(s, s, ssq[cc]);
        }
        __nv_bfloat162 p01 = __floats2bfloat162_rn(o[0], o[1]);
        __nv_bfloat162 p23 = __floats2bfloat162_rn(o[2], o[3]);
        if (cc < 8) {
            __nv_bfloat162* dst = (__nv_bfloat162*)&qd_s[cc][px0];
            dst[0] = p01; dst[1] = p23;
        } else {
            __nv_bfloat162* dst = (__nv_bfloat162*)&kd_s[cc - 8][px0];
            dst[0] = p01; dst[1] = p23;
        }
        __syncthreads();
    }

    /* phase 2: Gram accumulation over this block's 1024 pixels */
    float acc[64];
#pragma unroll
    for (int j = 0; j < 64; j++) { acc[j] = 0.f; }

#pragma unroll
    for (int j = 0; j < 4; j++) {
        int px = px0 + j;
        float qv[8], kv[8];
#pragma unroll
        for (int n = 0; n < 8; n++) {
            qv[n] = __bfloat162float(qd_s[n][px]);
            kv[n] = __bfloat162float(kd_s[n][px]);
        }
#pragma unroll
        for (int n = 0; n < 8; n++) {
#pragma unroll
            for (int m = 0; m < 8; m++) {
                acc[n * 8 + m] = fmaf(qv[n], kv[m], acc[n * 8 + m]);
            }
        }
    }

    if (tid < 80) red[tid] = 0.f;
    __syncthreads();
    int lnx = tid & 31;
#pragma unroll
    for (int j = 0; j < 64; j++) {
        float v = acc[j];
#pragma unroll
        for (int o2 = 16; o2 > 0; o2 >>= 1) { v += __shfl_down_sync(0xffffffffu, v, o2); }
        if (lnx == 0) atomicAdd(&red[j], v);
    }
#pragma unroll
    for (int j = 0; j < 16; j++) {
        float v = ssq[j];
#pragma unroll
        for (int o2 = 16; o2 > 0; o2 >>= 1) { v += __shfl_down_sync(0xffffffffu, v, o2); }
        if (lnx == 0) atomicAdd(&red[64 + j], v);
    }
    __syncthreads();
    if (tid < 64) {
        atomicAdd(&g_dots[bi * 64 + tid], red[tid]);
    } else if (tid < 80) {
        atomicAdd(&g_sumsq[bi * 16 + (tid - 64)], red[tid]);
    }
}

/* ---------------- softmax (tiny) ---------------- */
__global__ void softmax_kernel(const float* __restrict__ temp) {
    int t = threadIdx.x;
    if (t >= 32) return;
    int bi = t >> 3, n = t & 7;
    float T  = temp[0];
    float nq = fmaxf(sqrtf(g_sumsq[bi * 16 + n]), 1e-12f);
    float s[8], mx = -1e30f;
#pragma unroll
    for (int m = 0; m < 8; m++) {
        float nk = fmaxf(sqrtf(g_sumsq[bi * 16 + 8 + m]), 1e-12f);
        s[m] = g_dots[bi * 64 + n * 8 + m] / (nq * nk) * T;
        mx = fmaxf(mx, s[m]);
    }
    float sum = 0.f;
#pragma unroll
    for (int m = 0; m < 8; m++) {
        s[m] = expf(s[m] - mx);
        sum += s[m];
    }
    float inv = 1.f / sum;
#pragma unroll
    for (int m = 0; m < 8; m++) { g_attn[bi * 64 + n * 8 + m] = s[m] * inv; }
}

/* ======== fused dwconv(v) + attention mix ========
   out[n,c,p] = sum_m attn[n,m] * dwconv(v)[m,c,p]  */
#define ISSUE_VCH(mm, s) do { \
    int ch_ = 768 + (mm) * 48 + c; \
    const __nv_bfloat16* src_ = g_qkv + ((size_t)bi * 1152 + ch_) * HW; \
    if (tid < 160) { \
        int row_ = tid >> 4; \
        int col_ = (tid & 15) * 8; \
        int gy_ = y0 + row_ - 1; \
        int off_ = ((s) * 1280) + row_ * 128 + col_; \
        if (gy_ >= 0 && gy_ < HIMG) { \
            unsigned int dst_ = ibBase + (unsigned int)(off_ * 2); \
            CP_ASYNC16(dst_, src_ + gy_ * WIMG + col_); \
        } else { \
            *(float4*)((char*)inbuf + off_ * 2) = make_float4(0.f, 0.f, 0.f, 0.f); \
        } \
    } \
} while (0)

__global__ __launch_bounds__(256) void dwv_mix_kernel(const float* __restrict__ wdw,
                                                      const float* __restrict__ bdw) {
    __shared__ __align__(16) __nv_bfloat16 inbuf[2][1280];
    __shared__ __align__(16) __nv_bfloat16 vd_s[8][1024];
    __shared__ float at[64];

    int tid = threadIdx.x;
    int strip = blockIdx.x;
    int c  = blockIdx.y;
    int bi = blockIdx.z;
    int y0 = strip * 8;

    unsigned int ibBase = (unsigned int)__cvta_generic_to_shared(&inbuf[0][0]);

    if (tid < 64) at[tid] = g_attn[bi * 64 + tid];

    int r  = tid >> 5;
    int c0 = (tid & 31) * 4;
    int px0 = tid * 4;

    ISSUE_VCH(0, 0);
    CP_COMMIT();

    for (int mm = 0; mm < 8; mm++) {
        if (mm < 7) { ISSUE_VCH(mm + 1, (mm + 1) & 1); }
        CP_COMMIT();
        CP_WAIT1();
        __syncthreads();

        int ch = 768 + mm * 48 + c;
        float w[9];
#pragma unroll
        for (int i = 0; i < 9; i++) { w[i] = wdw[ch * 9 + i]; }
        float bv = bdw[ch];

        const __nv_bfloat16* ib = &inbuf[mm & 1][0];
        float vals[3][6];
#pragma unroll
        for (int dy = 0; dy < 3; dy++) {
#pragma unroll
            for (int dx = 0; dx < 6; dx++) {
                int cin = c0 - 1 + dx;
                vals[dy][dx] = (cin >= 0 && cin < 128)
                               ? __bfloat162float(ib[(r + dy) * 128 + cin]) : 0.f;
            }
        }
        float o[4];
#pragma unroll
        for (int j = 0; j < 4; j++) {
            float s = bv;
#pragma unroll
            for (int dy = 0; dy < 3; dy++) {
#pragma unroll
                for (int dx = 0; dx < 3; dx++) {
                    s = fmaf(w[dy * 3 + dx], vals[dy][j + dx], s);
                }
            }
            o[j] = s;
        }
        __nv_bfloat162* dst = (__nv_bfloat162*)&vd_s[mm][px0];
        dst[0] = __floats2bfloat162_rn(o[0], o[1]);
        dst[1] = __floats2bfloat162_rn(o[2], o[3]);
        __syncthreads();
    }

    /* mix: for this block's 1024 px, produce 8 head outputs */
    float v[8][4];
#pragma unroll
    for (int m = 0; m < 8; m++) {
#pragma unroll
        for (int j = 0; j < 4; j++) {
            v[m][j] = __bfloat162float(vd_s[m][px0 + j]);
        }
    }
    int pgl = strip * 1024 + px0;
#pragma unroll
    for (int n = 0; n < 8; n++) {
        float o0 = 0.f, o1 = 0.f, o2 = 0.f, o3 = 0.f;
#pragma unroll
        for (int m = 0; m < 8; m++) {
            float a = at[n * 8 + m];
            o0 = fmaf(a, v[m][0], o0);
            o1 = fmaf(a, v[m][1], o1);
            o2 = fmaf(a, v[m][2], o2);
            o3 = fmaf(a, v[m][3], o3);
        }
        __nv_bfloat162* dst =
            (__nv_bfloat162*)&g_mix[((size_t)bi * DIM + n * 48 + c) * HW + pgl];
        dst[0] = __floats2bfloat162_rn(o0, o1);
        dst[1] = __floats2bfloat162_rn(o2, o3);
    }
}

/* ---------------- launch ---------------- */
extern "C" void kernel_launch(void* const* d_in, const int* in_sizes, int n_in,
                              void* d_out, int out_size) {
    const float* x           = (const float*)d_in[0];
    const float* temperature = (const float*)d_in[1];
    const float* w_qkv       = (const float*)d_in[2];
    const float* b_qkv       = (const float*)d_in[3];
    const float* w_dw        = (const float*)d_in[4];
    const float* b_dw        = (const float*)d_in[5];
    const float* w_proj      = (const float*)d_in[6];
    const float* b_proj      = (const float*)d_in[7];
    float* out = (float*)d_out;

    cudaFuncSetAttribute(gemm_qkv_tc, cudaFuncAttributeMaxDynamicSharedMemorySize, SMEM_GEMM);
    cudaFuncSetAttribute(gemm_proj_tc, cudaFuncAttributeMaxDynamicSharedMemorySize, SMEM_GEMM);

    zero_kernel<<<1, 256>>>();
    convert_x<<<(BATCH * DIM * HW / 4) / 256, 256>>>(x);
    convert_w<<<(3 * DIM * DIM + DIM * DIM) / 256, 256>>>(w_qkv, w_proj);
    gemm_qkv_tc<<<dim3(512, 9), 256, SMEM_GEMM>>>(b_qkv);
    dwqk_dots_kernel<<<dim3(16, 48, BATCH), 256>>>(w_dw, b_dw);
    softmax_kernel<<<1, 32>>>(temperature);
    dwv_mix_kernel<<<dim3(16, 48, BATCH), 256>>>(w_dw, b_dw);
    gemm_proj_tc<<<dim3(512, 3), 256, SMEM_GEMM>>>(b_proj, x, out);
}